// round 15
// baseline (speedup 1.0000x reference)
#include <cuda_runtime.h>
#include <cuda_fp16.h>
#include <math.h>
#include <stdint.h>

// ============================ problem constants =============================
#define SEQ      2048
#define DMODEL   4096
#define DGROUP   512
#define DH       64
#define NHEADS   64
#define KDIM     4096
#define QKV_N    (DMODEL + 2 * DGROUP)   // 5120
#define KOFF     DMODEL
#define VOFF     (DMODEL + DGROUP)
#define WSCALE   64.0f
#define INVW     0.015625f               // 1/64

// ============================ scratch (device globals) ======================
__device__ __half g_xhi[SEQ * DMODEL];
__device__ __half g_xlo[SEQ * DMODEL];
__device__ __half g_QKV[SEQ * QKV_N];          // single fp16 QKV
__device__ __half g_Of[SEQ * DMODEL];
__device__ __half g_wqkvT_hi[QKV_N * KDIM];
__device__ __half g_wqkvT_lo[QKV_N * KDIM];
__device__ __half g_woT[DMODEL * KDIM];        // single fp16, unscaled
__device__ float  g_bqkv[QKV_N];

// ============================ PTX helpers ===================================
__device__ __forceinline__ uint32_t smem_u32(const void* p) {
    uint32_t a;
    asm("{ .reg .u64 t; cvta.to.shared.u64 t, %1; cvt.u32.u64 %0, t; }" : "=r"(a) : "l"(p));
    return a;
}
#define CP_ASYNC16(dst, src) \
    asm volatile("cp.async.cg.shared.global [%0], [%1], 16;" :: "r"(dst), "l"(src) : "memory")
#define CP_COMMIT() asm volatile("cp.async.commit_group;" ::: "memory")
#define CP_WAIT0()  asm volatile("cp.async.wait_group 0;" ::: "memory")
#define CP_WAIT1()  asm volatile("cp.async.wait_group 1;" ::: "memory")

__device__ __forceinline__ void ldsm_x4(uint32_t* r, uint32_t addr) {
    asm volatile("ldmatrix.sync.aligned.m8n8.x4.shared.b16 {%0,%1,%2,%3}, [%4];"
                 : "=r"(r[0]), "=r"(r[1]), "=r"(r[2]), "=r"(r[3]) : "r"(addr));
}
__device__ __forceinline__ void ldsm_x4_t(uint32_t* r, uint32_t addr) {
    asm volatile("ldmatrix.sync.aligned.m8n8.x4.trans.shared.b16 {%0,%1,%2,%3}, [%4];"
                 : "=r"(r[0]), "=r"(r[1]), "=r"(r[2]), "=r"(r[3]) : "r"(addr));
}
__device__ __forceinline__ void mma16816(float* d, const uint32_t* a, const uint32_t* b) {
    asm volatile(
        "mma.sync.aligned.m16n8k16.row.col.f32.f16.f16.f32 "
        "{%0,%1,%2,%3}, {%4,%5,%6,%7}, {%8,%9}, {%0,%1,%2,%3};"
        : "+f"(d[0]), "+f"(d[1]), "+f"(d[2]), "+f"(d[3])
        : "r"(a[0]), "r"(a[1]), "r"(a[2]), "r"(a[3]), "r"(b[0]), "r"(b[1]));
}
__device__ __forceinline__ uint32_t packh2(float lo, float hi) {
    uint32_t r;
    asm("cvt.rn.f16x2.f32 %0, %1, %2;" : "=r"(r) : "f"(hi), "f"(lo));
    return r;
}

// ============================ GEMM common ===================================
#define BM 128
#define BN 128
#define BK 32
#define NIT (KDIM / BK)          // 128
#define RS 40
#define MAT_BYTES (128 * RS * 2) // 10240

// -------- gemm3: 3-product split (A hi/lo, B hi/lo), single fp16 out -------
#define STAGE3 (4 * MAT_BYTES)
#define GEMM3_SMEM (2 * STAGE3)          // 81920
#define OFF_AHI 0
#define OFF_ALO (1 * MAT_BYTES)
#define OFF_BHI (2 * MAT_BYTES)
#define OFF_BLO (3 * MAT_BYTES)

__device__ __forceinline__ void g3_load(
    uint32_t st, int tid,
    const __half* __restrict__ Ahi, const __half* __restrict__ Alo,
    const __half* __restrict__ Bhi, const __half* __restrict__ Blo,
    int mBase, int nBase, int kt)
{
    const size_t k0 = (size_t)kt * BK;
    #pragma unroll
    for (int i = 0; i < 2; i++) {
        int e = tid + i * 256, r = e >> 2, c = e & 3;
        CP_ASYNC16(st + OFF_AHI + r * 80 + c * 16, Ahi + (size_t)(mBase + r) * KDIM + k0 + c * 8);
    }
    #pragma unroll
    for (int i = 0; i < 2; i++) {
        int e = tid + i * 256, r = e >> 2, c = e & 3;
        CP_ASYNC16(st + OFF_ALO + r * 80 + c * 16, Alo + (size_t)(mBase + r) * KDIM + k0 + c * 8);
    }
    #pragma unroll
    for (int i = 0; i < 2; i++) {
        int e = tid + i * 256, r = e >> 2, c = e & 3;
        CP_ASYNC16(st + OFF_BHI + r * 80 + c * 16, Bhi + (size_t)(nBase + r) * KDIM + k0 + c * 8);
    }
    #pragma unroll
    for (int i = 0; i < 2; i++) {
        int e = tid + i * 256, r = e >> 2, c = e & 3;
        CP_ASYNC16(st + OFF_BLO + r * 80 + c * 16, Blo + (size_t)(nBase + r) * KDIM + k0 + c * 8);
    }
    CP_COMMIT();
}

__global__ __launch_bounds__(256, 2)
void gemm3(const __half* __restrict__ Ahi, const __half* __restrict__ Alo,
           const __half* __restrict__ Bhi, const __half* __restrict__ Blo,
           const float* __restrict__ bias,
           __half* __restrict__ C, int Nglob)
{
    extern __shared__ char smc[];
    const uint32_t sbase = smem_u32(smc);
    const int tid  = threadIdx.x;
    const int wid  = tid >> 5, lane = tid & 31;
    const int wm   = wid & 3, wn = wid >> 2;
    const int mBase = blockIdx.y * BM, nBase = blockIdx.x * BN;

    const uint32_t a_lane =
        (uint32_t)(((wm * 32 + (lane & 15)) * RS + ((lane >> 4) << 3)) * 2);
    const uint32_t b_lane =
        (uint32_t)(((wn * 64 + ((lane >> 4) << 3) + (lane & 7)) * RS + (((lane >> 3) & 1) << 3)) * 2);

    float acc[2][8][4];
    #pragma unroll
    for (int i = 0; i < 2; i++)
        #pragma unroll
        for (int j = 0; j < 8; j++)
            #pragma unroll
            for (int c = 0; c < 4; c++)
                acc[i][j][c] = 0.0f;

    g3_load(sbase, tid, Ahi, Alo, Bhi, Blo, mBase, nBase, 0);
    g3_load(sbase + STAGE3, tid, Ahi, Alo, Bhi, Blo, mBase, nBase, 1);

    for (int it = 0; it < NIT; it++) {
        if (it + 2 < NIT) { CP_WAIT1(); } else { CP_WAIT0(); }
        __syncthreads();
        const uint32_t st = sbase + (it & 1) * STAGE3;

        #pragma unroll
        for (int kk = 0; kk < 2; kk++) {
            const uint32_t koff = kk * 32;
            uint32_t bh[4][4], bl[4][4];
            #pragma unroll
            for (int j = 0; j < 4; j++) {
                ldsm_x4(bh[j], st + OFF_BHI + b_lane + j * (16 * RS * 2) + koff);
                ldsm_x4(bl[j], st + OFF_BLO + b_lane + j * (16 * RS * 2) + koff);
            }
            #pragma unroll
            for (int i = 0; i < 2; i++) {
                uint32_t ah[4], al[4];
                ldsm_x4(ah, st + OFF_AHI + a_lane + i * (16 * RS * 2) + koff);
                ldsm_x4(al, st + OFF_ALO + a_lane + i * (16 * RS * 2) + koff);
                #pragma unroll
                for (int jj = 0; jj < 8; jj++) {
                    const uint32_t* bhp = &bh[jj >> 1][(jj & 1) * 2];
                    const uint32_t* blp = &bl[jj >> 1][(jj & 1) * 2];
                    mma16816(acc[i][jj], ah, bhp);
                    mma16816(acc[i][jj], ah, blp);
                    mma16816(acc[i][jj], al, bhp);
                }
            }
        }
        __syncthreads();
        if (it + 2 < NIT)
            g3_load(sbase + (it & 1) * STAGE3, tid, Ahi, Alo, Bhi, Blo, mBase, nBase, it + 2);
    }

    const int r0 = mBase + wm * 32 + (lane >> 2);
    const int c0 = nBase + wn * 64 + (lane & 3) * 2;
    #pragma unroll
    for (int i = 0; i < 2; i++) {
        #pragma unroll
        for (int jj = 0; jj < 8; jj++) {
            const int col = c0 + jj * 8;
            const float b0 = __ldg(&bias[col]), b1 = __ldg(&bias[col + 1]);
            const int row = r0 + i * 16;
            float u0 = acc[i][jj][0] * INVW + b0, u1 = acc[i][jj][1] * INVW + b1;
            float u2 = acc[i][jj][2] * INVW + b0, u3 = acc[i][jj][3] * INVW + b1;
            *(uint32_t*)&C[(size_t)row * Nglob + col]       = packh2(u0, u1);
            *(uint32_t*)&C[(size_t)(row + 8) * Nglob + col] = packh2(u2, u3);
        }
    }
}

// -------- gemm1: plain fp16 GEMM (A single, B single), fp32 out + bias -----
#define STAGE1 (2 * MAT_BYTES)           // 20480
#define GEMM1_SMEM (2 * STAGE1)          // 40960
#define OFF1_AF 0
#define OFF1_BF (1 * MAT_BYTES)

__device__ __forceinline__ void g1_load(
    uint32_t st, int tid,
    const __half* __restrict__ Af, const __half* __restrict__ Bf,
    int mBase, int nBase, int kt)
{
    const size_t k0 = (size_t)kt * BK;
    #pragma unroll
    for (int i = 0; i < 2; i++) {
        int e = tid + i * 256, r = e >> 2, c = e & 3;
        CP_ASYNC16(st + OFF1_AF + r * 80 + c * 16, Af + (size_t)(mBase + r) * KDIM + k0 + c * 8);
    }
    #pragma unroll
    for (int i = 0; i < 2; i++) {
        int e = tid + i * 256, r = e >> 2, c = e & 3;
        CP_ASYNC16(st + OFF1_BF + r * 80 + c * 16, Bf + (size_t)(nBase + r) * KDIM + k0 + c * 8);
    }
    CP_COMMIT();
}

__global__ __launch_bounds__(256, 2)
void gemm1(const __half* __restrict__ Af, const __half* __restrict__ Bf,
           const float* __restrict__ bias, float* __restrict__ Cf, int Nglob)
{
    extern __shared__ char smc[];
    const uint32_t sbase = smem_u32(smc);
    const int tid  = threadIdx.x;
    const int wid  = tid >> 5, lane = tid & 31;
    const int wm   = wid & 3, wn = wid >> 2;
    const int mBase = blockIdx.y * BM, nBase = blockIdx.x * BN;

    const uint32_t a_lane =
        (uint32_t)(((wm * 32 + (lane & 15)) * RS + ((lane >> 4) << 3)) * 2);
    const uint32_t b_lane =
        (uint32_t)(((wn * 64 + ((lane >> 4) << 3) + (lane & 7)) * RS + (((lane >> 3) & 1) << 3)) * 2);

    float acc[2][8][4];
    #pragma unroll
    for (int i = 0; i < 2; i++)
        #pragma unroll
        for (int j = 0; j < 8; j++)
            #pragma unroll
            for (int c = 0; c < 4; c++)
                acc[i][j][c] = 0.0f;

    g1_load(sbase, tid, Af, Bf, mBase, nBase, 0);
    g1_load(sbase + STAGE1, tid, Af, Bf, mBase, nBase, 1);

    for (int it = 0; it < NIT; it++) {
        if (it + 2 < NIT) { CP_WAIT1(); } else { CP_WAIT0(); }
        __syncthreads();
        const uint32_t st = sbase + (it & 1) * STAGE1;

        #pragma unroll
        for (int kk = 0; kk < 2; kk++) {
            const uint32_t koff = kk * 32;
            uint32_t bf[4][4];
            #pragma unroll
            for (int j = 0; j < 4; j++)
                ldsm_x4(bf[j], st + OFF1_BF + b_lane + j * (16 * RS * 2) + koff);
            #pragma unroll
            for (int i = 0; i < 2; i++) {
                uint32_t af[4];
                ldsm_x4(af, st + OFF1_AF + a_lane + i * (16 * RS * 2) + koff);
                #pragma unroll
                for (int jj = 0; jj < 8; jj++)
                    mma16816(acc[i][jj], af, &bf[jj >> 1][(jj & 1) * 2]);
            }
        }
        __syncthreads();
        if (it + 2 < NIT)
            g1_load(sbase + (it & 1) * STAGE1, tid, Af, Bf, mBase, nBase, it + 2);
    }

    const int r0 = mBase + wm * 32 + (lane >> 2);
    const int c0 = nBase + wn * 64 + (lane & 3) * 2;
    #pragma unroll
    for (int i = 0; i < 2; i++) {
        #pragma unroll
        for (int jj = 0; jj < 8; jj++) {
            const int col = c0 + jj * 8;
            const float b0 = __ldg(&bias[col]), b1 = __ldg(&bias[col + 1]);
            const int row = r0 + i * 16;
            *(float2*)&Cf[(size_t)row * Nglob + col] =
                make_float2(acc[i][jj][0] + b0, acc[i][jj][1] + b1);
            *(float2*)&Cf[(size_t)(row + 8) * Nglob + col] =
                make_float2(acc[i][jj][2] + b0, acc[i][jj][3] + b1);
        }
    }
}

// ============================ conversion kernels ============================
// split: 16 floats per thread (4 independent float4 loads -> MLP 4)
__global__ void split_kernel(const float* __restrict__ in,
                             __half* __restrict__ hi, __half* __restrict__ lo, int n)
{
    int base = (blockIdx.x * blockDim.x + threadIdx.x) * 16;
    if (base >= n) return;
    float4 v[4];
    #pragma unroll
    for (int j = 0; j < 4; j++)
        v[j] = *(const float4*)(in + base + j * 4);
    #pragma unroll
    for (int j = 0; j < 4; j++) {
        __half h0 = __float2half_rn(v[j].x), h1 = __float2half_rn(v[j].y);
        __half h2 = __float2half_rn(v[j].z), h3 = __float2half_rn(v[j].w);
        __half l0 = __float2half_rn(v[j].x - __half2float(h0));
        __half l1 = __float2half_rn(v[j].y - __half2float(h1));
        __half l2 = __float2half_rn(v[j].z - __half2float(h2));
        __half l3 = __float2half_rn(v[j].w - __half2float(h3));
        __half2* H = (__half2*)(hi + base + j * 4);
        __half2* L = (__half2*)(lo + base + j * 4);
        H[0] = {h0, h1}; H[1] = {h2, h3};
        L[0] = {l0, l1}; L[1] = {l2, l3};
    }
}

// w[K, N] -> t[N, K], scaled by 64, split into fp16 hi/lo.
// Tile 32(k) x 128(n); 4 float4 loads/thread; padded smem (stride 129).
__global__ void transpose_split(const float* __restrict__ w,
                                __half* __restrict__ thi, __half* __restrict__ tlo,
                                int K, int N)
{
    __shared__ float s[32][129];
    const int kb = blockIdx.y * 32, nb = blockIdx.x * 128;
    const int tid = threadIdx.x;
    #pragma unroll
    for (int i = 0; i < 4; i++) {
        int e = tid + i * 256, r = e >> 5, c = (e & 31) * 4;
        float4 v = *(const float4*)&w[(size_t)(kb + r) * N + nb + c];
        s[r][c] = v.x; s[r][c + 1] = v.y; s[r][c + 2] = v.z; s[r][c + 3] = v.w;
    }
    __syncthreads();
    const int nloc = tid >> 1, k0 = (tid & 1) * 16;
    const size_t obase = (size_t)(nb + nloc) * K + kb + k0;
    #pragma unroll
    for (int j = 0; j < 8; j++) {
        float va = s[k0 + 2 * j][nloc] * WSCALE;
        float vb = s[k0 + 2 * j + 1][nloc] * WSCALE;
        __half ha = __float2half_rn(va), hb = __float2half_rn(vb);
        __half la = __float2half_rn(va - __half2float(ha));
        __half lb = __float2half_rn(vb - __half2float(hb));
        ((__half2*)(thi + obase))[j] = {ha, hb};
        ((__half2*)(tlo + obase))[j] = {la, lb};
    }
}

// w[K, N] -> t[N, K], single fp16 (unscaled). Same tiling.
__global__ void transpose_half(const float* __restrict__ w,
                               __half* __restrict__ t, int K, int N)
{
    __shared__ float s[32][129];
    const int kb = blockIdx.y * 32, nb = blockIdx.x * 128;
    const int tid = threadIdx.x;
    #pragma unroll
    for (int i = 0; i < 4; i++) {
        int e = tid + i * 256, r = e >> 5, c = (e & 31) * 4;
        float4 v = *(const float4*)&w[(size_t)(kb + r) * N + nb + c];
        s[r][c] = v.x; s[r][c + 1] = v.y; s[r][c + 2] = v.z; s[r][c + 3] = v.w;
    }
    __syncthreads();
    const int nloc = tid >> 1, k0 = (tid & 1) * 16;
    const size_t obase = (size_t)(nb + nloc) * K + kb + k0;
    #pragma unroll
    for (int j = 0; j < 8; j++) {
        __half ha = __float2half_rn(s[k0 + 2 * j][nloc]);
        __half hb = __float2half_rn(s[k0 + 2 * j + 1][nloc]);
        ((__half2*)(t + obase))[j] = {ha, hb};
    }
}

// ============================ flash attention ===============================
// Pure fp16: QK 1-product (Q×K-hi), PV 1-product (P×V-hi).
#define FRS 72
#define FQ_BYTES  (128 * FRS * 2)        // 18432
#define FKV_BYTES (64 * FRS * 2)         // 9216
#define FSTG_BYTES (2 * FKV_BYTES)       // K, V
#define FSTG_OFF  FQ_BYTES
#define FLASH_SMEM (FSTG_OFF + 2 * FSTG_BYTES)   // 55296
#define FNIT (SEQ / 64)

__device__ __forceinline__ void flash_load_kv(
    uint32_t st, int tid,
    const __half* __restrict__ QKV,
    int krow0, int kcol0, int vcol0)
{
    #pragma unroll
    for (int i = 0; i < 2; i++) {
        int e = tid + i * 256, r = e >> 3, c = e & 7;
        CP_ASYNC16(st + r * (FRS * 2) + c * 16, QKV + (size_t)(krow0 + r) * QKV_N + kcol0 + c * 8);
    }
    #pragma unroll
    for (int i = 0; i < 2; i++) {
        int e = tid + i * 256, r = e >> 3, c = e & 7;
        CP_ASYNC16(st + FKV_BYTES + r * (FRS * 2) + c * 16, QKV + (size_t)(krow0 + r) * QKV_N + vcol0 + c * 8);
    }
    CP_COMMIT();
}

__global__ __launch_bounds__(256, 1)
void flash_mma(const __half* __restrict__ QKV, __half* __restrict__ Of)
{
    extern __shared__ char smc[];
    const uint32_t sbase = smem_u32(smc);
    const int tid  = threadIdx.x;
    const int wid  = tid >> 5, lane = tid & 31;
    const int head = blockIdx.y, g = head >> 3;
    const int qrow0 = blockIdx.x * 128;
    const int qcol0 = head * DH;
    const int kcol0 = KOFF + g * DH;
    const int vcol0 = VOFF + g * DH;

    #pragma unroll
    for (int i = 0; i < 4; i++) {
        int e = tid + i * 256, r = e >> 3, c = e & 7;
        CP_ASYNC16(sbase + r * (FRS * 2) + c * 16, QKV + (size_t)(qrow0 + r) * QKV_N + qcol0 + c * 8);
    }
    flash_load_kv(sbase + FSTG_OFF, tid, QKV, 0, kcol0, vcol0);
    flash_load_kv(sbase + FSTG_OFF + FSTG_BYTES, tid, QKV, 64, kcol0, vcol0);

    const uint32_t a_lane =
        (uint32_t)(((wid * 16 + (lane & 15)) * FRS + ((lane >> 4) << 3)) * 2);
    const uint32_t b_lane =
        (uint32_t)(((((lane >> 4) << 3) + (lane & 7)) * FRS + (((lane >> 3) & 1) << 3)) * 2);
    const uint32_t v_lane =
        (uint32_t)(((((lane >> 3) & 1) * 8 + (lane & 7)) * FRS + ((lane >> 4) << 3)) * 2);

    float oacc[8][4];
    #pragma unroll
    for (int t = 0; t < 8; t++)
        #pragma unroll
        for (int c = 0; c < 4; c++) oacc[t][c] = 0.0f;
    float m0 = -INFINITY, m1 = -INFINITY, l0 = 0.0f, l1 = 0.0f;

    for (int it = 0; it < FNIT; it++) {
        if (it < FNIT - 1) { CP_WAIT1(); } else { CP_WAIT0(); }
        __syncthreads();
        const uint32_t st = sbase + FSTG_OFF + (it & 1) * FSTG_BYTES;

        float sacc[8][4];
        #pragma unroll
        for (int t = 0; t < 8; t++)
            #pragma unroll
            for (int c = 0; c < 4; c++) sacc[t][c] = 0.0f;

        // S = Q * K : 1 product
        #pragma unroll
        for (int kk = 0; kk < 4; kk++) {
            const uint32_t koff = kk * 32;
            uint32_t ah[4];
            ldsm_x4(ah, sbase + a_lane + koff);
            uint32_t bh[4][4];
            #pragma unroll
            for (int j = 0; j < 4; j++)
                ldsm_x4(bh[j], st + b_lane + j * (16 * FRS * 2) + koff);
            #pragma unroll
            for (int t = 0; t < 8; t++)
                mma16816(sacc[t], ah, &bh[t >> 1][(t & 1) * 2]);
        }

        const float scale = 0.125f;
        float mx0 = -INFINITY, mx1 = -INFINITY;
        #pragma unroll
        for (int t = 0; t < 8; t++) {
            #pragma unroll
            for (int c = 0; c < 4; c++) sacc[t][c] *= scale;
            mx0 = fmaxf(mx0, fmaxf(sacc[t][0], sacc[t][1]));
            mx1 = fmaxf(mx1, fmaxf(sacc[t][2], sacc[t][3]));
        }
        mx0 = fmaxf(mx0, __shfl_xor_sync(0xffffffffu, mx0, 1));
        mx0 = fmaxf(mx0, __shfl_xor_sync(0xffffffffu, mx0, 2));
        mx1 = fmaxf(mx1, __shfl_xor_sync(0xffffffffu, mx1, 1));
        mx1 = fmaxf(mx1, __shfl_xor_sync(0xffffffffu, mx1, 2));
        const float mn0 = fmaxf(m0, mx0), mn1 = fmaxf(m1, mx1);
        const float corr0 = __expf(m0 - mn0), corr1 = __expf(m1 - mn1);
        m0 = mn0; m1 = mn1;

        float sum0 = 0.0f, sum1 = 0.0f;
        uint32_t pf[8][2];
        #pragma unroll
        for (int t = 0; t < 8; t++) {
            float p0 = __expf(sacc[t][0] - mn0), p1 = __expf(sacc[t][1] - mn0);
            float p2 = __expf(sacc[t][2] - mn1), p3 = __expf(sacc[t][3] - mn1);
            sum0 += p0 + p1; sum1 += p2 + p3;
            pf[t][0] = packh2(p0, p1);
            pf[t][1] = packh2(p2, p3);
        }
        sum0 += __shfl_xor_sync(0xffffffffu, sum0, 1);
        sum0 += __shfl_xor_sync(0xffffffffu, sum0, 2);
        sum1 += __shfl_xor_sync(0xffffffffu, sum1, 1);
        sum1 += __shfl_xor_sync(0xffffffffu, sum1, 2);
        l0 = l0 * corr0 + sum0;
        l1 = l1 * corr1 + sum1;
        #pragma unroll
        for (int t = 0; t < 8; t++) {
            oacc[t][0] *= corr0; oacc[t][1] *= corr0;
            oacc[t][2] *= corr1; oacc[t][3] *= corr1;
        }

        // O += P V : 1 product
        #pragma unroll
        for (int j = 0; j < 4; j++) {
            uint32_t ap[4] = { pf[2 * j][0], pf[2 * j][1], pf[2 * j + 1][0], pf[2 * j + 1][1] };
            #pragma unroll
            for (int nb = 0; nb < 4; nb++) {
                uint32_t vaddr = st + FKV_BYTES + v_lane + j * (16 * FRS * 2) + nb * 32;
                uint32_t vh[4];
                ldsm_x4_t(vh, vaddr);
                mma16816(oacc[2 * nb],     ap, &vh[0]);
                mma16816(oacc[2 * nb + 1], ap, &vh[2]);
            }
        }

        __syncthreads();
        if (it + 2 < FNIT)
            flash_load_kv(st, tid, QKV, (it + 2) * 64, kcol0, vcol0);
    }

    const float inv0 = 1.0f / l0, inv1 = 1.0f / l1;
    const int row0 = qrow0 + wid * 16 + (lane >> 2);
    const int row1 = row0 + 8;
    #pragma unroll
    for (int t = 0; t < 8; t++) {
        const int col = qcol0 + t * 8 + (lane & 3) * 2;
        *(uint32_t*)&Of[(size_t)row0 * DMODEL + col] =
            packh2(oacc[t][0] * inv0, oacc[t][1] * inv0);
        *(uint32_t*)&Of[(size_t)row1 * DMODEL + col] =
            packh2(oacc[t][2] * inv1, oacc[t][3] * inv1);
    }
}

// ============================ kernel_launch =================================
extern "C" void kernel_launch(void* const* d_in, const int* in_sizes, int n_in,
                              void* d_out, int out_size)
{
    const float* x  = (const float*)d_in[0];
    const float* wq = (const float*)d_in[1];
    const float* bq = (const float*)d_in[2];
    const float* wk = (const float*)d_in[3];
    const float* bk = (const float*)d_in[4];
    const float* wv = (const float*)d_in[5];
    const float* bv = (const float*)d_in[6];
    const float* wo = (const float*)d_in[7];
    const float* bo = (const float*)d_in[8];
    float* out = (float*)d_out;

    __half *xhi, *xlo, *QKV, *Of;
    __half *wqkvh, *wqkvl, *woT;
    float* bqkv;
    cudaGetSymbolAddress((void**)&xhi, g_xhi);
    cudaGetSymbolAddress((void**)&xlo, g_xlo);
    cudaGetSymbolAddress((void**)&QKV, g_QKV);
    cudaGetSymbolAddress((void**)&Of, g_Of);
    cudaGetSymbolAddress((void**)&wqkvh, g_wqkvT_hi);
    cudaGetSymbolAddress((void**)&wqkvl, g_wqkvT_lo);
    cudaGetSymbolAddress((void**)&woT, g_woT);
    cudaGetSymbolAddress((void**)&bqkv, g_bqkv);

    cudaFuncSetAttribute(gemm3, cudaFuncAttributeMaxDynamicSharedMemorySize, GEMM3_SMEM);
    cudaFuncSetAttribute(gemm1, cudaFuncAttributeMaxDynamicSharedMemorySize, GEMM1_SMEM);
    cudaFuncSetAttribute(flash_mma, cudaFuncAttributeMaxDynamicSharedMemorySize, FLASH_SMEM);

    const int nX = SEQ * DMODEL;

    cudaMemcpyAsync(bqkv,        bq, DMODEL * sizeof(float), cudaMemcpyDeviceToDevice);
    cudaMemcpyAsync(bqkv + KOFF, bk, DGROUP * sizeof(float), cudaMemcpyDeviceToDevice);
    cudaMemcpyAsync(bqkv + VOFF, bv, DGROUP * sizeof(float), cudaMemcpyDeviceToDevice);

    split_kernel<<<nX / (256 * 16), 256>>>(x, xhi, xlo, nX);
    transpose_split<<<dim3(DMODEL / 128, KDIM / 32), 256>>>(wq, wqkvh, wqkvl, KDIM, DMODEL);
    transpose_split<<<dim3(DGROUP / 128, KDIM / 32), 256>>>(
        wk, wqkvh + (size_t)KOFF * KDIM, wqkvl + (size_t)KOFF * KDIM, KDIM, DGROUP);
    transpose_split<<<dim3(DGROUP / 128, KDIM / 32), 256>>>(
        wv, wqkvh + (size_t)VOFF * KDIM, wqkvl + (size_t)VOFF * KDIM, KDIM, DGROUP);
    transpose_half<<<dim3(DMODEL / 128, KDIM / 32), 256>>>(wo, woT, KDIM, DMODEL);

    // fused QKV projection (3-product, single fp16 out): [2048,4096] @ [4096,5120]
    gemm3<<<dim3(QKV_N / BN, SEQ / BM), 256, GEMM3_SMEM>>>(
        xhi, xlo, wqkvh, wqkvl, bqkv, QKV, QKV_N);

    flash_mma<<<dim3(SEQ / 128, NHEADS), 256, FLASH_SMEM>>>(QKV, Of);

    // O projection (1-product): [2048,4096] @ [4096,4096] -> fp32 out
    gemm1<<<dim3(DMODEL / BN, SEQ / BM), 256, GEMM1_SMEM>>>(Of, woT, bo, out, DMODEL);
}

// round 16
// speedup vs baseline: 1.0793x; 1.0793x over previous
#include <cuda_runtime.h>
#include <cuda_fp16.h>
#include <math.h>
#include <stdint.h>

// ============================ problem constants =============================
#define SEQ      2048
#define DMODEL   4096
#define DGROUP   512
#define DH       64
#define NHEADS   64
#define KDIM     4096
#define QKV_N    (DMODEL + 2 * DGROUP)   // 5120
#define KOFF     DMODEL
#define VOFF     (DMODEL + DGROUP)
#define WSCALE   64.0f
#define INVW     0.015625f               // 1/64

// ============================ scratch (device globals) ======================
__device__ __half g_xhi[SEQ * DMODEL];
__device__ __half g_xlo[SEQ * DMODEL];
__device__ __half g_QKV[SEQ * QKV_N];          // single fp16 QKV
__device__ __half g_Of[SEQ * DMODEL];
__device__ __half g_wqkvT_hi[QKV_N * KDIM];
__device__ __half g_wqkvT_lo[QKV_N * KDIM];
__device__ __half g_woT[DMODEL * KDIM];        // single fp16, unscaled
__device__ float  g_bqkv[QKV_N];

// ============================ PTX helpers ===================================
__device__ __forceinline__ uint32_t smem_u32(const void* p) {
    uint32_t a;
    asm("{ .reg .u64 t; cvta.to.shared.u64 t, %1; cvt.u32.u64 %0, t; }" : "=r"(a) : "l"(p));
    return a;
}
#define CP_ASYNC16(dst, src) \
    asm volatile("cp.async.cg.shared.global [%0], [%1], 16;" :: "r"(dst), "l"(src) : "memory")
#define CP_COMMIT() asm volatile("cp.async.commit_group;" ::: "memory")
#define CP_WAIT0()  asm volatile("cp.async.wait_group 0;" ::: "memory")
#define CP_WAIT1()  asm volatile("cp.async.wait_group 1;" ::: "memory")

__device__ __forceinline__ void ldsm_x4(uint32_t* r, uint32_t addr) {
    asm volatile("ldmatrix.sync.aligned.m8n8.x4.shared.b16 {%0,%1,%2,%3}, [%4];"
                 : "=r"(r[0]), "=r"(r[1]), "=r"(r[2]), "=r"(r[3]) : "r"(addr));
}
__device__ __forceinline__ void ldsm_x4_t(uint32_t* r, uint32_t addr) {
    asm volatile("ldmatrix.sync.aligned.m8n8.x4.trans.shared.b16 {%0,%1,%2,%3}, [%4];"
                 : "=r"(r[0]), "=r"(r[1]), "=r"(r[2]), "=r"(r[3]) : "r"(addr));
}
__device__ __forceinline__ void mma16816(float* d, const uint32_t* a, const uint32_t* b) {
    asm volatile(
        "mma.sync.aligned.m16n8k16.row.col.f32.f16.f16.f32 "
        "{%0,%1,%2,%3}, {%4,%5,%6,%7}, {%8,%9}, {%0,%1,%2,%3};"
        : "+f"(d[0]), "+f"(d[1]), "+f"(d[2]), "+f"(d[3])
        : "r"(a[0]), "r"(a[1]), "r"(a[2]), "r"(a[3]), "r"(b[0]), "r"(b[1]));
}
__device__ __forceinline__ uint32_t packh2(float lo, float hi) {
    uint32_t r;
    asm("cvt.rn.f16x2.f32 %0, %1, %2;" : "=r"(r) : "f"(hi), "f"(lo));
    return r;
}

// ============================ GEMM common ===================================
#define BM 128
#define BN 128
#define BK 32
#define NIT (KDIM / BK)          // 128
#define RS 40
#define MAT_BYTES (128 * RS * 2) // 10240

// -------- gemm3: 3-product split (A hi/lo, B hi/lo), single fp16 out -------
#define STAGE3 (4 * MAT_BYTES)
#define GEMM3_SMEM (2 * STAGE3)          // 81920
#define OFF_AHI 0
#define OFF_ALO (1 * MAT_BYTES)
#define OFF_BHI (2 * MAT_BYTES)
#define OFF_BLO (3 * MAT_BYTES)

__device__ __forceinline__ void g3_load(
    uint32_t st, int tid,
    const __half* __restrict__ Ahi, const __half* __restrict__ Alo,
    const __half* __restrict__ Bhi, const __half* __restrict__ Blo,
    int mBase, int nBase, int kt)
{
    const size_t k0 = (size_t)kt * BK;
    #pragma unroll
    for (int i = 0; i < 2; i++) {
        int e = tid + i * 256, r = e >> 2, c = e & 3;
        CP_ASYNC16(st + OFF_AHI + r * 80 + c * 16, Ahi + (size_t)(mBase + r) * KDIM + k0 + c * 8);
    }
    #pragma unroll
    for (int i = 0; i < 2; i++) {
        int e = tid + i * 256, r = e >> 2, c = e & 3;
        CP_ASYNC16(st + OFF_ALO + r * 80 + c * 16, Alo + (size_t)(mBase + r) * KDIM + k0 + c * 8);
    }
    #pragma unroll
    for (int i = 0; i < 2; i++) {
        int e = tid + i * 256, r = e >> 2, c = e & 3;
        CP_ASYNC16(st + OFF_BHI + r * 80 + c * 16, Bhi + (size_t)(nBase + r) * KDIM + k0 + c * 8);
    }
    #pragma unroll
    for (int i = 0; i < 2; i++) {
        int e = tid + i * 256, r = e >> 2, c = e & 3;
        CP_ASYNC16(st + OFF_BLO + r * 80 + c * 16, Blo + (size_t)(nBase + r) * KDIM + k0 + c * 8);
    }
    CP_COMMIT();
}

__global__ __launch_bounds__(256, 2)
void gemm3(const __half* __restrict__ Ahi, const __half* __restrict__ Alo,
           const __half* __restrict__ Bhi, const __half* __restrict__ Blo,
           const float* __restrict__ bias,
           __half* __restrict__ C, int Nglob)
{
    extern __shared__ char smc[];
    const uint32_t sbase = smem_u32(smc);
    const int tid  = threadIdx.x;
    const int wid  = tid >> 5, lane = tid & 31;
    const int wm   = wid & 3, wn = wid >> 2;
    const int mBase = blockIdx.y * BM, nBase = blockIdx.x * BN;

    const uint32_t a_lane =
        (uint32_t)(((wm * 32 + (lane & 15)) * RS + ((lane >> 4) << 3)) * 2);
    const uint32_t b_lane =
        (uint32_t)(((wn * 64 + ((lane >> 4) << 3) + (lane & 7)) * RS + (((lane >> 3) & 1) << 3)) * 2);

    float acc[2][8][4];
    #pragma unroll
    for (int i = 0; i < 2; i++)
        #pragma unroll
        for (int j = 0; j < 8; j++)
            #pragma unroll
            for (int c = 0; c < 4; c++)
                acc[i][j][c] = 0.0f;

    g3_load(sbase, tid, Ahi, Alo, Bhi, Blo, mBase, nBase, 0);
    g3_load(sbase + STAGE3, tid, Ahi, Alo, Bhi, Blo, mBase, nBase, 1);

    for (int it = 0; it < NIT; it++) {
        if (it + 2 < NIT) { CP_WAIT1(); } else { CP_WAIT0(); }
        __syncthreads();
        const uint32_t st = sbase + (it & 1) * STAGE3;

        #pragma unroll
        for (int kk = 0; kk < 2; kk++) {
            const uint32_t koff = kk * 32;
            uint32_t bh[4][4], bl[4][4];
            #pragma unroll
            for (int j = 0; j < 4; j++) {
                ldsm_x4(bh[j], st + OFF_BHI + b_lane + j * (16 * RS * 2) + koff);
                ldsm_x4(bl[j], st + OFF_BLO + b_lane + j * (16 * RS * 2) + koff);
            }
            #pragma unroll
            for (int i = 0; i < 2; i++) {
                uint32_t ah[4], al[4];
                ldsm_x4(ah, st + OFF_AHI + a_lane + i * (16 * RS * 2) + koff);
                ldsm_x4(al, st + OFF_ALO + a_lane + i * (16 * RS * 2) + koff);
                #pragma unroll
                for (int jj = 0; jj < 8; jj++) {
                    const uint32_t* bhp = &bh[jj >> 1][(jj & 1) * 2];
                    const uint32_t* blp = &bl[jj >> 1][(jj & 1) * 2];
                    mma16816(acc[i][jj], ah, bhp);
                    mma16816(acc[i][jj], ah, blp);
                    mma16816(acc[i][jj], al, bhp);
                }
            }
        }
        __syncthreads();
        if (it + 2 < NIT)
            g3_load(sbase + (it & 1) * STAGE3, tid, Ahi, Alo, Bhi, Blo, mBase, nBase, it + 2);
    }

    const int r0 = mBase + wm * 32 + (lane >> 2);
    const int c0 = nBase + wn * 64 + (lane & 3) * 2;
    #pragma unroll
    for (int i = 0; i < 2; i++) {
        #pragma unroll
        for (int jj = 0; jj < 8; jj++) {
            const int col = c0 + jj * 8;
            const float b0 = __ldg(&bias[col]), b1 = __ldg(&bias[col + 1]);
            const int row = r0 + i * 16;
            float u0 = acc[i][jj][0] * INVW + b0, u1 = acc[i][jj][1] * INVW + b1;
            float u2 = acc[i][jj][2] * INVW + b0, u3 = acc[i][jj][3] * INVW + b1;
            *(uint32_t*)&C[(size_t)row * Nglob + col]       = packh2(u0, u1);
            *(uint32_t*)&C[(size_t)(row + 8) * Nglob + col] = packh2(u2, u3);
        }
    }
}

// -------- gemm1: plain fp16 GEMM (A single, B single), fp32 out + bias -----
#define STAGE1 (2 * MAT_BYTES)           // 20480
#define GEMM1_SMEM (2 * STAGE1)          // 40960
#define OFF1_AF 0
#define OFF1_BF (1 * MAT_BYTES)

__device__ __forceinline__ void g1_load(
    uint32_t st, int tid,
    const __half* __restrict__ Af, const __half* __restrict__ Bf,
    int mBase, int nBase, int kt)
{
    const size_t k0 = (size_t)kt * BK;
    #pragma unroll
    for (int i = 0; i < 2; i++) {
        int e = tid + i * 256, r = e >> 2, c = e & 3;
        CP_ASYNC16(st + OFF1_AF + r * 80 + c * 16, Af + (size_t)(mBase + r) * KDIM + k0 + c * 8);
    }
    #pragma unroll
    for (int i = 0; i < 2; i++) {
        int e = tid + i * 256, r = e >> 2, c = e & 3;
        CP_ASYNC16(st + OFF1_BF + r * 80 + c * 16, Bf + (size_t)(nBase + r) * KDIM + k0 + c * 8);
    }
    CP_COMMIT();
}

__global__ __launch_bounds__(256, 2)
void gemm1(const __half* __restrict__ Af, const __half* __restrict__ Bf,
           const float* __restrict__ bias, float* __restrict__ Cf, int Nglob)
{
    extern __shared__ char smc[];
    const uint32_t sbase = smem_u32(smc);
    const int tid  = threadIdx.x;
    const int wid  = tid >> 5, lane = tid & 31;
    const int wm   = wid & 3, wn = wid >> 2;
    const int mBase = blockIdx.y * BM, nBase = blockIdx.x * BN;

    const uint32_t a_lane =
        (uint32_t)(((wm * 32 + (lane & 15)) * RS + ((lane >> 4) << 3)) * 2);
    const uint32_t b_lane =
        (uint32_t)(((wn * 64 + ((lane >> 4) << 3) + (lane & 7)) * RS + (((lane >> 3) & 1) << 3)) * 2);

    float acc[2][8][4];
    #pragma unroll
    for (int i = 0; i < 2; i++)
        #pragma unroll
        for (int j = 0; j < 8; j++)
            #pragma unroll
            for (int c = 0; c < 4; c++)
                acc[i][j][c] = 0.0f;

    g1_load(sbase, tid, Af, Bf, mBase, nBase, 0);
    g1_load(sbase + STAGE1, tid, Af, Bf, mBase, nBase, 1);

    for (int it = 0; it < NIT; it++) {
        if (it + 2 < NIT) { CP_WAIT1(); } else { CP_WAIT0(); }
        __syncthreads();
        const uint32_t st = sbase + (it & 1) * STAGE1;

        #pragma unroll
        for (int kk = 0; kk < 2; kk++) {
            const uint32_t koff = kk * 32;
            uint32_t bf[4][4];
            #pragma unroll
            for (int j = 0; j < 4; j++)
                ldsm_x4(bf[j], st + OFF1_BF + b_lane + j * (16 * RS * 2) + koff);
            #pragma unroll
            for (int i = 0; i < 2; i++) {
                uint32_t af[4];
                ldsm_x4(af, st + OFF1_AF + a_lane + i * (16 * RS * 2) + koff);
                #pragma unroll
                for (int jj = 0; jj < 8; jj++)
                    mma16816(acc[i][jj], af, &bf[jj >> 1][(jj & 1) * 2]);
            }
        }
        __syncthreads();
        if (it + 2 < NIT)
            g1_load(sbase + (it & 1) * STAGE1, tid, Af, Bf, mBase, nBase, it + 2);
    }

    const int r0 = mBase + wm * 32 + (lane >> 2);
    const int c0 = nBase + wn * 64 + (lane & 3) * 2;
    #pragma unroll
    for (int i = 0; i < 2; i++) {
        #pragma unroll
        for (int jj = 0; jj < 8; jj++) {
            const int col = c0 + jj * 8;
            const float b0 = __ldg(&bias[col]), b1 = __ldg(&bias[col + 1]);
            const int row = r0 + i * 16;
            *(float2*)&Cf[(size_t)row * Nglob + col] =
                make_float2(acc[i][jj][0] + b0, acc[i][jj][1] + b1);
            *(float2*)&Cf[(size_t)(row + 8) * Nglob + col] =
                make_float2(acc[i][jj][2] + b0, acc[i][jj][3] + b1);
        }
    }
}

// ============================ conversion kernels (R14-proven) ===============
__global__ void split_kernel(const float* __restrict__ in,
                             __half* __restrict__ hi, __half* __restrict__ lo, int n)
{
    int idx = (blockIdx.x * blockDim.x + threadIdx.x) * 4;
    if (idx >= n) return;
    float4 v = *(const float4*)(in + idx);
    __half h0 = __float2half_rn(v.x), h1 = __float2half_rn(v.y);
    __half h2 = __float2half_rn(v.z), h3 = __float2half_rn(v.w);
    __half l0 = __float2half_rn(v.x - __half2float(h0));
    __half l1 = __float2half_rn(v.y - __half2float(h1));
    __half l2 = __float2half_rn(v.z - __half2float(h2));
    __half l3 = __float2half_rn(v.w - __half2float(h3));
    __half2* H = (__half2*)(hi + idx);
    __half2* L = (__half2*)(lo + idx);
    H[0] = {h0, h1}; H[1] = {h2, h3};
    L[0] = {l0, l1}; L[1] = {l2, l3};
}

// w[K, N] -> t[N, K], scaled by 64, split into fp16 hi/lo
__global__ void transpose_split(const float* __restrict__ w,
                                __half* __restrict__ thi, __half* __restrict__ tlo,
                                int K, int N)
{
    __shared__ float tile[32][33];
    const int kb = blockIdx.y * 32, nb = blockIdx.x * 32;
    const int tx = threadIdx.x, ty = threadIdx.y;
    #pragma unroll
    for (int j = 0; j < 4; j++) {
        int r = ty + 8 * j;
        tile[r][tx] = w[(size_t)(kb + r) * N + nb + tx];
    }
    __syncthreads();
    #pragma unroll
    for (int j = 0; j < 4; j++) {
        int r = ty + 8 * j;
        float v = tile[tx][r] * WSCALE;
        __half h = __float2half_rn(v);
        __half l = __float2half_rn(v - __half2float(h));
        size_t o = (size_t)(nb + r) * K + kb + tx;
        thi[o] = h; tlo[o] = l;
    }
}

// w[K, N] -> t[N, K], single fp16 (unscaled)
__global__ void transpose_half(const float* __restrict__ w,
                               __half* __restrict__ t, int K, int N)
{
    __shared__ float tile[32][33];
    const int kb = blockIdx.y * 32, nb = blockIdx.x * 32;
    const int tx = threadIdx.x, ty = threadIdx.y;
    #pragma unroll
    for (int j = 0; j < 4; j++) {
        int r = ty + 8 * j;
        tile[r][tx] = w[(size_t)(kb + r) * N + nb + tx];
    }
    __syncthreads();
    #pragma unroll
    for (int j = 0; j < 4; j++) {
        int r = ty + 8 * j;
        t[(size_t)(nb + r) * K + kb + tx] = __float2half_rn(tile[tx][r]);
    }
}

// ============================ flash attention ===============================
// Pure fp16: QK 1-product (Q×K-hi), PV 1-product (P×V-hi). Occupancy 2.
#define FRS 72
#define FQ_BYTES  (128 * FRS * 2)        // 18432
#define FKV_BYTES (64 * FRS * 2)         // 9216
#define FSTG_BYTES (2 * FKV_BYTES)       // K, V
#define FSTG_OFF  FQ_BYTES
#define FLASH_SMEM (FSTG_OFF + 2 * FSTG_BYTES)   // 55296
#define FNIT (SEQ / 64)

__device__ __forceinline__ void flash_load_kv(
    uint32_t st, int tid,
    const __half* __restrict__ QKV,
    int krow0, int kcol0, int vcol0)
{
    #pragma unroll
    for (int i = 0; i < 2; i++) {
        int e = tid + i * 256, r = e >> 3, c = e & 7;
        CP_ASYNC16(st + r * (FRS * 2) + c * 16, QKV + (size_t)(krow0 + r) * QKV_N + kcol0 + c * 8);
    }
    #pragma unroll
    for (int i = 0; i < 2; i++) {
        int e = tid + i * 256, r = e >> 3, c = e & 7;
        CP_ASYNC16(st + FKV_BYTES + r * (FRS * 2) + c * 16, QKV + (size_t)(krow0 + r) * QKV_N + vcol0 + c * 8);
    }
    CP_COMMIT();
}

__global__ __launch_bounds__(256, 2)
void flash_mma(const __half* __restrict__ QKV, __half* __restrict__ Of)
{
    extern __shared__ char smc[];
    const uint32_t sbase = smem_u32(smc);
    const int tid  = threadIdx.x;
    const int wid  = tid >> 5, lane = tid & 31;
    const int head = blockIdx.y, g = head >> 3;
    const int qrow0 = blockIdx.x * 128;
    const int qcol0 = head * DH;
    const int kcol0 = KOFF + g * DH;
    const int vcol0 = VOFF + g * DH;

    #pragma unroll
    for (int i = 0; i < 4; i++) {
        int e = tid + i * 256, r = e >> 3, c = e & 7;
        CP_ASYNC16(sbase + r * (FRS * 2) + c * 16, QKV + (size_t)(qrow0 + r) * QKV_N + qcol0 + c * 8);
    }
    flash_load_kv(sbase + FSTG_OFF, tid, QKV, 0, kcol0, vcol0);
    flash_load_kv(sbase + FSTG_OFF + FSTG_BYTES, tid, QKV, 64, kcol0, vcol0);

    const uint32_t a_lane =
        (uint32_t)(((wid * 16 + (lane & 15)) * FRS + ((lane >> 4) << 3)) * 2);
    const uint32_t b_lane =
        (uint32_t)(((((lane >> 4) << 3) + (lane & 7)) * FRS + (((lane >> 3) & 1) << 3)) * 2);
    const uint32_t v_lane =
        (uint32_t)(((((lane >> 3) & 1) * 8 + (lane & 7)) * FRS + ((lane >> 4) << 3)) * 2);

    float oacc[8][4];
    #pragma unroll
    for (int t = 0; t < 8; t++)
        #pragma unroll
        for (int c = 0; c < 4; c++) oacc[t][c] = 0.0f;
    float m0 = -INFINITY, m1 = -INFINITY, l0 = 0.0f, l1 = 0.0f;

    for (int it = 0; it < FNIT; it++) {
        if (it < FNIT - 1) { CP_WAIT1(); } else { CP_WAIT0(); }
        __syncthreads();
        const uint32_t st = sbase + FSTG_OFF + (it & 1) * FSTG_BYTES;

        float sacc[8][4];
        #pragma unroll
        for (int t = 0; t < 8; t++)
            #pragma unroll
            for (int c = 0; c < 4; c++) sacc[t][c] = 0.0f;

        // S = Q * K : 1 product
        #pragma unroll
        for (int kk = 0; kk < 4; kk++) {
            const uint32_t koff = kk * 32;
            uint32_t ah[4];
            ldsm_x4(ah, sbase + a_lane + koff);
            uint32_t bh[4][4];
            #pragma unroll
            for (int j = 0; j < 4; j++)
                ldsm_x4(bh[j], st + b_lane + j * (16 * FRS * 2) + koff);
            #pragma unroll
            for (int t = 0; t < 8; t++)
                mma16816(sacc[t], ah, &bh[t >> 1][(t & 1) * 2]);
        }

        const float scale = 0.125f;
        float mx0 = -INFINITY, mx1 = -INFINITY;
        #pragma unroll
        for (int t = 0; t < 8; t++) {
            #pragma unroll
            for (int c = 0; c < 4; c++) sacc[t][c] *= scale;
            mx0 = fmaxf(mx0, fmaxf(sacc[t][0], sacc[t][1]));
            mx1 = fmaxf(mx1, fmaxf(sacc[t][2], sacc[t][3]));
        }
        mx0 = fmaxf(mx0, __shfl_xor_sync(0xffffffffu, mx0, 1));
        mx0 = fmaxf(mx0, __shfl_xor_sync(0xffffffffu, mx0, 2));
        mx1 = fmaxf(mx1, __shfl_xor_sync(0xffffffffu, mx1, 1));
        mx1 = fmaxf(mx1, __shfl_xor_sync(0xffffffffu, mx1, 2));
        const float mn0 = fmaxf(m0, mx0), mn1 = fmaxf(m1, mx1);
        const float corr0 = __expf(m0 - mn0), corr1 = __expf(m1 - mn1);
        m0 = mn0; m1 = mn1;

        float sum0 = 0.0f, sum1 = 0.0f;
        uint32_t pf[8][2];
        #pragma unroll
        for (int t = 0; t < 8; t++) {
            float p0 = __expf(sacc[t][0] - mn0), p1 = __expf(sacc[t][1] - mn0);
            float p2 = __expf(sacc[t][2] - mn1), p3 = __expf(sacc[t][3] - mn1);
            sum0 += p0 + p1; sum1 += p2 + p3;
            pf[t][0] = packh2(p0, p1);
            pf[t][1] = packh2(p2, p3);
        }
        sum0 += __shfl_xor_sync(0xffffffffu, sum0, 1);
        sum0 += __shfl_xor_sync(0xffffffffu, sum0, 2);
        sum1 += __shfl_xor_sync(0xffffffffu, sum1, 1);
        sum1 += __shfl_xor_sync(0xffffffffu, sum1, 2);
        l0 = l0 * corr0 + sum0;
        l1 = l1 * corr1 + sum1;
        #pragma unroll
        for (int t = 0; t < 8; t++) {
            oacc[t][0] *= corr0; oacc[t][1] *= corr0;
            oacc[t][2] *= corr1; oacc[t][3] *= corr1;
        }

        // O += P V : 1 product
        #pragma unroll
        for (int j = 0; j < 4; j++) {
            uint32_t ap[4] = { pf[2 * j][0], pf[2 * j][1], pf[2 * j + 1][0], pf[2 * j + 1][1] };
            #pragma unroll
            for (int nb = 0; nb < 4; nb++) {
                uint32_t vaddr = st + FKV_BYTES + v_lane + j * (16 * FRS * 2) + nb * 32;
                uint32_t vh[4];
                ldsm_x4_t(vh, vaddr);
                mma16816(oacc[2 * nb],     ap, &vh[0]);
                mma16816(oacc[2 * nb + 1], ap, &vh[2]);
            }
        }

        __syncthreads();
        if (it + 2 < FNIT)
            flash_load_kv(st, tid, QKV, (it + 2) * 64, kcol0, vcol0);
    }

    const float inv0 = 1.0f / l0, inv1 = 1.0f / l1;
    const int row0 = qrow0 + wid * 16 + (lane >> 2);
    const int row1 = row0 + 8;
    #pragma unroll
    for (int t = 0; t < 8; t++) {
        const int col = qcol0 + t * 8 + (lane & 3) * 2;
        *(uint32_t*)&Of[(size_t)row0 * DMODEL + col] =
            packh2(oacc[t][0] * inv0, oacc[t][1] * inv0);
        *(uint32_t*)&Of[(size_t)row1 * DMODEL + col] =
            packh2(oacc[t][2] * inv1, oacc[t][3] * inv1);
    }
}

// ============================ kernel_launch =================================
extern "C" void kernel_launch(void* const* d_in, const int* in_sizes, int n_in,
                              void* d_out, int out_size)
{
    const float* x  = (const float*)d_in[0];
    const float* wq = (const float*)d_in[1];
    const float* bq = (const float*)d_in[2];
    const float* wk = (const float*)d_in[3];
    const float* bk = (const float*)d_in[4];
    const float* wv = (const float*)d_in[5];
    const float* bv = (const float*)d_in[6];
    const float* wo = (const float*)d_in[7];
    const float* bo = (const float*)d_in[8];
    float* out = (float*)d_out;

    __half *xhi, *xlo, *QKV, *Of;
    __half *wqkvh, *wqkvl, *woT;
    float* bqkv;
    cudaGetSymbolAddress((void**)&xhi, g_xhi);
    cudaGetSymbolAddress((void**)&xlo, g_xlo);
    cudaGetSymbolAddress((void**)&QKV, g_QKV);
    cudaGetSymbolAddress((void**)&Of, g_Of);
    cudaGetSymbolAddress((void**)&wqkvh, g_wqkvT_hi);
    cudaGetSymbolAddress((void**)&wqkvl, g_wqkvT_lo);
    cudaGetSymbolAddress((void**)&woT, g_woT);
    cudaGetSymbolAddress((void**)&bqkv, g_bqkv);

    cudaFuncSetAttribute(gemm3, cudaFuncAttributeMaxDynamicSharedMemorySize, GEMM3_SMEM);
    cudaFuncSetAttribute(gemm1, cudaFuncAttributeMaxDynamicSharedMemorySize, GEMM1_SMEM);
    cudaFuncSetAttribute(flash_mma, cudaFuncAttributeMaxDynamicSharedMemorySize, FLASH_SMEM);

    const int nX = SEQ * DMODEL;

    cudaMemcpyAsync(bqkv,        bq, DMODEL * sizeof(float), cudaMemcpyDeviceToDevice);
    cudaMemcpyAsync(bqkv + KOFF, bk, DGROUP * sizeof(float), cudaMemcpyDeviceToDevice);
    cudaMemcpyAsync(bqkv + VOFF, bv, DGROUP * sizeof(float), cudaMemcpyDeviceToDevice);

    split_kernel<<<nX / (256 * 4), 256>>>(x, xhi, xlo, nX);
    transpose_split<<<dim3(DMODEL / 32, KDIM / 32), dim3(32, 8)>>>(wq, wqkvh, wqkvl, KDIM, DMODEL);
    transpose_split<<<dim3(DGROUP / 32, KDIM / 32), dim3(32, 8)>>>(
        wk, wqkvh + (size_t)KOFF * KDIM, wqkvl + (size_t)KOFF * KDIM, KDIM, DGROUP);
    transpose_split<<<dim3(DGROUP / 32, KDIM / 32), dim3(32, 8)>>>(
        wv, wqkvh + (size_t)VOFF * KDIM, wqkvl + (size_t)VOFF * KDIM, KDIM, DGROUP);
    transpose_half<<<dim3(DMODEL / 32, KDIM / 32), dim3(32, 8)>>>(wo, woT, KDIM, DMODEL);

    // fused QKV projection (3-product, single fp16 out): [2048,4096] @ [4096,5120]
    gemm3<<<dim3(QKV_N / BN, SEQ / BM), 256, GEMM3_SMEM>>>(
        xhi, xlo, wqkvh, wqkvl, bqkv, QKV, QKV_N);

    flash_mma<<<dim3(SEQ / 128, NHEADS), 256, FLASH_SMEM>>>(QKV, Of);

    // O projection (1-product): [2048,4096] @ [4096,4096] -> fp32 out
    gemm1<<<dim3(DMODEL / BN, SEQ / BM), 256, GEMM1_SMEM>>>(Of, woT, bo, out, DMODEL);
}

// round 17
// speedup vs baseline: 1.1319x; 1.0487x over previous
#include <cuda_runtime.h>
#include <cuda_fp16.h>
#include <math.h>
#include <stdint.h>

// ============================ problem constants =============================
#define SEQ      2048
#define DMODEL   4096
#define DGROUP   512
#define DH       64
#define NHEADS   64
#define KDIM     4096
#define QKV_N    (DMODEL + 2 * DGROUP)   // 5120
#define KOFF     DMODEL
#define VOFF     (DMODEL + DGROUP)
#define WSCALE   64.0f
#define INVW     0.015625f               // 1/64

// ============================ scratch (device globals) ======================
__device__ __half g_xhi[SEQ * DMODEL];
__device__ __half g_xlo[SEQ * DMODEL];
__device__ __half g_QKV[SEQ * QKV_N];
__device__ __half g_Of[SEQ * DMODEL];
__device__ __half g_wqkvF_hi[KDIM * QKV_N];    // fused [K=4096, 5120], native layout
__device__ __half g_wqkvF_lo[KDIM * QKV_N];
__device__ __half g_woF[KDIM * DMODEL];        // [K, N] native, single fp16 unscaled
__device__ float  g_bqkv[QKV_N];

// ============================ PTX helpers ===================================
__device__ __forceinline__ uint32_t smem_u32(const void* p) {
    uint32_t a;
    asm("{ .reg .u64 t; cvta.to.shared.u64 t, %1; cvt.u32.u64 %0, t; }" : "=r"(a) : "l"(p));
    return a;
}
#define CP_ASYNC16(dst, src) \
    asm volatile("cp.async.cg.shared.global [%0], [%1], 16;" :: "r"(dst), "l"(src) : "memory")
#define CP_COMMIT() asm volatile("cp.async.commit_group;" ::: "memory")
#define CP_WAIT0()  asm volatile("cp.async.wait_group 0;" ::: "memory")
#define CP_WAIT1()  asm volatile("cp.async.wait_group 1;" ::: "memory")

__device__ __forceinline__ void ldsm_x4(uint32_t* r, uint32_t addr) {
    asm volatile("ldmatrix.sync.aligned.m8n8.x4.shared.b16 {%0,%1,%2,%3}, [%4];"
                 : "=r"(r[0]), "=r"(r[1]), "=r"(r[2]), "=r"(r[3]) : "r"(addr));
}
__device__ __forceinline__ void ldsm_x4_t(uint32_t* r, uint32_t addr) {
    asm volatile("ldmatrix.sync.aligned.m8n8.x4.trans.shared.b16 {%0,%1,%2,%3}, [%4];"
                 : "=r"(r[0]), "=r"(r[1]), "=r"(r[2]), "=r"(r[3]) : "r"(addr));
}
__device__ __forceinline__ void mma16816(float* d, const uint32_t* a, const uint32_t* b) {
    asm volatile(
        "mma.sync.aligned.m16n8k16.row.col.f32.f16.f16.f32 "
        "{%0,%1,%2,%3}, {%4,%5,%6,%7}, {%8,%9}, {%0,%1,%2,%3};"
        : "+f"(d[0]), "+f"(d[1]), "+f"(d[2]), "+f"(d[3])
        : "r"(a[0]), "r"(a[1]), "r"(a[2]), "r"(a[3]), "r"(b[0]), "r"(b[1]));
}
__device__ __forceinline__ uint32_t packh2(float lo, float hi) {
    uint32_t r;
    asm("cvt.rn.f16x2.f32 %0, %1, %2;" : "=r"(r) : "f"(hi), "f"(lo));
    return r;
}

// ============================ GEMM common ===================================
#define BM 128
#define BN 128
#define BK 32
#define NIT (KDIM / BK)          // 128
#define RS 40                    // A smem stride (halfs)
#define RSB 136                  // B smem stride (halfs) for [k][n] tiles (128+8)
#define MAT_BYTES  (128 * RS * 2)    // 10240 (A)
#define BMAT_BYTES (32 * RSB * 2)    // 8704  (B)

// -------- gemm3: 3-product split; B native [K,N], trans-ldsm ---------------
#define STAGE3 (2 * MAT_BYTES + 2 * BMAT_BYTES)  // 37888
#define GEMM3_SMEM (2 * STAGE3)                   // 75776
#define OFF_AHI 0
#define OFF_ALO MAT_BYTES
#define OFF_BHI (2 * MAT_BYTES)
#define OFF_BLO (2 * MAT_BYTES + BMAT_BYTES)

__device__ __forceinline__ void g3_load(
    uint32_t st, int tid,
    const __half* __restrict__ Ahi, const __half* __restrict__ Alo,
    const __half* __restrict__ Bhi, const __half* __restrict__ Blo,
    int mBase, int nBase, int kt, int Nglob)
{
    const size_t k0 = (size_t)kt * BK;
    // A: 128 rows x 4 chunks (row-major along K)
    #pragma unroll
    for (int i = 0; i < 2; i++) {
        int e = tid + i * 256, r = e >> 2, c = e & 3;
        CP_ASYNC16(st + OFF_AHI + r * 80 + c * 16, Ahi + (size_t)(mBase + r) * KDIM + k0 + c * 8);
    }
    #pragma unroll
    for (int i = 0; i < 2; i++) {
        int e = tid + i * 256, r = e >> 2, c = e & 3;
        CP_ASYNC16(st + OFF_ALO + r * 80 + c * 16, Alo + (size_t)(mBase + r) * KDIM + k0 + c * 8);
    }
    // B: 32 k-rows x 16 chunks of 16B (row-major along N, coalesced)
    #pragma unroll
    for (int i = 0; i < 2; i++) {
        int e = tid + i * 256, r = e >> 4, c = e & 15;
        CP_ASYNC16(st + OFF_BHI + r * 272 + c * 16, Bhi + (k0 + r) * (size_t)Nglob + nBase + c * 8);
    }
    #pragma unroll
    for (int i = 0; i < 2; i++) {
        int e = tid + i * 256, r = e >> 4, c = e & 15;
        CP_ASYNC16(st + OFF_BLO + r * 272 + c * 16, Blo + (k0 + r) * (size_t)Nglob + nBase + c * 8);
    }
    CP_COMMIT();
}

__global__ __launch_bounds__(256, 2)
void gemm3(const __half* __restrict__ Ahi, const __half* __restrict__ Alo,
           const __half* __restrict__ Bhi, const __half* __restrict__ Blo,
           const float* __restrict__ bias,
           __half* __restrict__ C, int Nglob)
{
    extern __shared__ char smc[];
    const uint32_t sbase = smem_u32(smc);
    const int tid  = threadIdx.x;
    const int wid  = tid >> 5, lane = tid & 31;
    const int wm   = wid & 3, wn = wid >> 2;
    const int mBase = blockIdx.y * BM, nBase = blockIdx.x * BN;

    const uint32_t a_lane =
        (uint32_t)(((wm * 32 + (lane & 15)) * RS + ((lane >> 4) << 3)) * 2);
    // trans-ldsm B lane (flash v_lane pattern): row=k in 16-group, col=n 0/8, +warp n
    const uint32_t bt_lane =
        (uint32_t)(((((lane >> 3) & 1) * 8 + (lane & 7)) * RSB + ((lane >> 4) << 3) + wn * 64) * 2);

    float acc[2][8][4];
    #pragma unroll
    for (int i = 0; i < 2; i++)
        #pragma unroll
        for (int j = 0; j < 8; j++)
            #pragma unroll
            for (int c = 0; c < 4; c++)
                acc[i][j][c] = 0.0f;

    g3_load(sbase, tid, Ahi, Alo, Bhi, Blo, mBase, nBase, 0, Nglob);
    g3_load(sbase + STAGE3, tid, Ahi, Alo, Bhi, Blo, mBase, nBase, 1, Nglob);

    for (int it = 0; it < NIT; it++) {
        if (it + 2 < NIT) { CP_WAIT1(); } else { CP_WAIT0(); }
        __syncthreads();
        const uint32_t st = sbase + (it & 1) * STAGE3;

        #pragma unroll
        for (int kk = 0; kk < 2; kk++) {
            const uint32_t koffA = kk * 32;                 // A: 16 halfs along k
            const uint32_t bbase = st + kk * (16 * RSB * 2) + bt_lane;
            uint32_t bh[4][4], bl[4][4];
            #pragma unroll
            for (int j = 0; j < 4; j++) {                   // 4 n-blocks of 16
                ldsm_x4_t(bh[j], bbase + OFF_BHI + j * 32);
                ldsm_x4_t(bl[j], bbase + OFF_BLO + j * 32);
            }
            #pragma unroll
            for (int i = 0; i < 2; i++) {
                uint32_t ah[4], al[4];
                ldsm_x4(ah, st + OFF_AHI + a_lane + i * (16 * RS * 2) + koffA);
                ldsm_x4(al, st + OFF_ALO + a_lane + i * (16 * RS * 2) + koffA);
                #pragma unroll
                for (int jj = 0; jj < 8; jj++) {
                    const uint32_t* bhp = &bh[jj >> 1][(jj & 1) * 2];
                    const uint32_t* blp = &bl[jj >> 1][(jj & 1) * 2];
                    mma16816(acc[i][jj], ah, bhp);
                    mma16816(acc[i][jj], ah, blp);
                    mma16816(acc[i][jj], al, bhp);
                }
            }
        }
        __syncthreads();
        if (it + 2 < NIT)
            g3_load(sbase + (it & 1) * STAGE3, tid, Ahi, Alo, Bhi, Blo, mBase, nBase, it + 2, Nglob);
    }

    const int r0 = mBase + wm * 32 + (lane >> 2);
    const int c0 = nBase + wn * 64 + (lane & 3) * 2;
    #pragma unroll
    for (int i = 0; i < 2; i++) {
        #pragma unroll
        for (int jj = 0; jj < 8; jj++) {
            const int col = c0 + jj * 8;
            const float b0 = __ldg(&bias[col]), b1 = __ldg(&bias[col + 1]);
            const int row = r0 + i * 16;
            float u0 = acc[i][jj][0] * INVW + b0, u1 = acc[i][jj][1] * INVW + b1;
            float u2 = acc[i][jj][2] * INVW + b0, u3 = acc[i][jj][3] * INVW + b1;
            *(uint32_t*)&C[(size_t)row * Nglob + col]       = packh2(u0, u1);
            *(uint32_t*)&C[(size_t)(row + 8) * Nglob + col] = packh2(u2, u3);
        }
    }
}

// -------- gemm1: plain fp16; B native [K,N], trans-ldsm --------------------
#define STAGE1 (MAT_BYTES + BMAT_BYTES)  // 18944
#define GEMM1_SMEM (2 * STAGE1)          // 37888
#define OFF1_AF 0
#define OFF1_BF MAT_BYTES

__device__ __forceinline__ void g1_load(
    uint32_t st, int tid,
    const __half* __restrict__ Af, const __half* __restrict__ Bf,
    int mBase, int nBase, int kt, int Nglob)
{
    const size_t k0 = (size_t)kt * BK;
    #pragma unroll
    for (int i = 0; i < 2; i++) {
        int e = tid + i * 256, r = e >> 2, c = e & 3;
        CP_ASYNC16(st + OFF1_AF + r * 80 + c * 16, Af + (size_t)(mBase + r) * KDIM + k0 + c * 8);
    }
    #pragma unroll
    for (int i = 0; i < 2; i++) {
        int e = tid + i * 256, r = e >> 4, c = e & 15;
        CP_ASYNC16(st + OFF1_BF + r * 272 + c * 16, Bf + (k0 + r) * (size_t)Nglob + nBase + c * 8);
    }
    CP_COMMIT();
}

__global__ __launch_bounds__(256, 2)
void gemm1(const __half* __restrict__ Af, const __half* __restrict__ Bf,
           const float* __restrict__ bias, float* __restrict__ Cf, int Nglob)
{
    extern __shared__ char smc[];
    const uint32_t sbase = smem_u32(smc);
    const int tid  = threadIdx.x;
    const int wid  = tid >> 5, lane = tid & 31;
    const int wm   = wid & 3, wn = wid >> 2;
    const int mBase = blockIdx.y * BM, nBase = blockIdx.x * BN;

    const uint32_t a_lane =
        (uint32_t)(((wm * 32 + (lane & 15)) * RS + ((lane >> 4) << 3)) * 2);
    const uint32_t bt_lane =
        (uint32_t)(((((lane >> 3) & 1) * 8 + (lane & 7)) * RSB + ((lane >> 4) << 3) + wn * 64) * 2);

    float acc[2][8][4];
    #pragma unroll
    for (int i = 0; i < 2; i++)
        #pragma unroll
        for (int j = 0; j < 8; j++)
            #pragma unroll
            for (int c = 0; c < 4; c++)
                acc[i][j][c] = 0.0f;

    g1_load(sbase, tid, Af, Bf, mBase, nBase, 0, Nglob);
    g1_load(sbase + STAGE1, tid, Af, Bf, mBase, nBase, 1, Nglob);

    for (int it = 0; it < NIT; it++) {
        if (it + 2 < NIT) { CP_WAIT1(); } else { CP_WAIT0(); }
        __syncthreads();
        const uint32_t st = sbase + (it & 1) * STAGE1;

        #pragma unroll
        for (int kk = 0; kk < 2; kk++) {
            const uint32_t koffA = kk * 32;
            const uint32_t bbase = st + OFF1_BF + kk * (16 * RSB * 2) + bt_lane;
            uint32_t bf[4][4];
            #pragma unroll
            for (int j = 0; j < 4; j++)
                ldsm_x4_t(bf[j], bbase + j * 32);
            #pragma unroll
            for (int i = 0; i < 2; i++) {
                uint32_t af[4];
                ldsm_x4(af, st + OFF1_AF + a_lane + i * (16 * RS * 2) + koffA);
                #pragma unroll
                for (int jj = 0; jj < 8; jj++)
                    mma16816(acc[i][jj], af, &bf[jj >> 1][(jj & 1) * 2]);
            }
        }
        __syncthreads();
        if (it + 2 < NIT)
            g1_load(sbase + (it & 1) * STAGE1, tid, Af, Bf, mBase, nBase, it + 2, Nglob);
    }

    const int r0 = mBase + wm * 32 + (lane >> 2);
    const int c0 = nBase + wn * 64 + (lane & 3) * 2;
    #pragma unroll
    for (int i = 0; i < 2; i++) {
        #pragma unroll
        for (int jj = 0; jj < 8; jj++) {
            const int col = c0 + jj * 8;
            const float b0 = __ldg(&bias[col]), b1 = __ldg(&bias[col + 1]);
            const int row = r0 + i * 16;
            *(float2*)&Cf[(size_t)row * Nglob + col] =
                make_float2(acc[i][jj][0] + b0, acc[i][jj][1] + b1);
            *(float2*)&Cf[(size_t)(row + 8) * Nglob + col] =
                make_float2(acc[i][jj][2] + b0, acc[i][jj][3] + b1);
        }
    }
}

// ============================ conversion kernels ============================
// x: fp32 -> fp16 hi/lo, unscaled, same layout (R14-proven)
__global__ void split_kernel(const float* __restrict__ in,
                             __half* __restrict__ hi, __half* __restrict__ lo, int n)
{
    int idx = (blockIdx.x * blockDim.x + threadIdx.x) * 4;
    if (idx >= n) return;
    float4 v = *(const float4*)(in + idx);
    __half h0 = __float2half_rn(v.x), h1 = __float2half_rn(v.y);
    __half h2 = __float2half_rn(v.z), h3 = __float2half_rn(v.w);
    __half l0 = __float2half_rn(v.x - __half2float(h0));
    __half l1 = __float2half_rn(v.y - __half2float(h1));
    __half l2 = __float2half_rn(v.z - __half2float(h2));
    __half l3 = __float2half_rn(v.w - __half2float(h3));
    __half2* H = (__half2*)(hi + idx);
    __half2* L = (__half2*)(lo + idx);
    H[0] = {h0, h1}; H[1] = {h2, h3};
    L[0] = {l0, l1}; L[1] = {l2, l3};
}

// weight: fp32 [K, Nw] -> scaled fp16 hi/lo written into fused [K, QKV_N] at colOff
__global__ void split_w(const float* __restrict__ w,
                        __half* __restrict__ hi, __half* __restrict__ lo,
                        int Nw, int colOff)
{
    int idx = (blockIdx.x * blockDim.x + threadIdx.x) * 4;
    int k = idx / Nw, j = idx - k * Nw;
    float4 v = *(const float4*)(w + idx);
    float s0 = v.x * WSCALE, s1 = v.y * WSCALE, s2 = v.z * WSCALE, s3 = v.w * WSCALE;
    __half h0 = __float2half_rn(s0), h1 = __float2half_rn(s1);
    __half h2 = __float2half_rn(s2), h3 = __float2half_rn(s3);
    __half l0 = __float2half_rn(s0 - __half2float(h0));
    __half l1 = __float2half_rn(s1 - __half2float(h1));
    __half l2 = __float2half_rn(s2 - __half2float(h2));
    __half l3 = __float2half_rn(s3 - __half2float(h3));
    size_t o = (size_t)k * QKV_N + colOff + j;
    __half2* H = (__half2*)(hi + o);
    __half2* L = (__half2*)(lo + o);
    H[0] = {h0, h1}; H[1] = {h2, h3};
    L[0] = {l0, l1}; L[1] = {l2, l3};
}

// wo: fp32 -> single fp16, same layout, unscaled
__global__ void conv_half(const float* __restrict__ in, __half* __restrict__ o, int n)
{
    int idx = (blockIdx.x * blockDim.x + threadIdx.x) * 4;
    if (idx >= n) return;
    float4 v = *(const float4*)(in + idx);
    __half2* O = (__half2*)(o + idx);
    O[0] = {__float2half_rn(v.x), __float2half_rn(v.y)};
    O[1] = {__float2half_rn(v.z), __float2half_rn(v.w)};
}

// ============================ flash attention (R14-exact, occ 1) ============
#define FRS 72
#define FQ_BYTES  (128 * FRS * 2)
#define FKV_BYTES (64 * FRS * 2)
#define FSTG_BYTES (2 * FKV_BYTES)
#define FSTG_OFF  FQ_BYTES
#define FLASH_SMEM (FSTG_OFF + 2 * FSTG_BYTES)   // 55296
#define FNIT (SEQ / 64)

__device__ __forceinline__ void flash_load_kv(
    uint32_t st, int tid,
    const __half* __restrict__ QKV,
    int krow0, int kcol0, int vcol0)
{
    #pragma unroll
    for (int i = 0; i < 2; i++) {
        int e = tid + i * 256, r = e >> 3, c = e & 7;
        CP_ASYNC16(st + r * (FRS * 2) + c * 16, QKV + (size_t)(krow0 + r) * QKV_N + kcol0 + c * 8);
    }
    #pragma unroll
    for (int i = 0; i < 2; i++) {
        int e = tid + i * 256, r = e >> 3, c = e & 7;
        CP_ASYNC16(st + FKV_BYTES + r * (FRS * 2) + c * 16, QKV + (size_t)(krow0 + r) * QKV_N + vcol0 + c * 8);
    }
    CP_COMMIT();
}

__global__ __launch_bounds__(256, 1)
void flash_mma(const __half* __restrict__ QKV, __half* __restrict__ Of)
{
    extern __shared__ char smc[];
    const uint32_t sbase = smem_u32(smc);
    const int tid  = threadIdx.x;
    const int wid  = tid >> 5, lane = tid & 31;
    const int head = blockIdx.y, g = head >> 3;
    const int qrow0 = blockIdx.x * 128;
    const int qcol0 = head * DH;
    const int kcol0 = KOFF + g * DH;
    const int vcol0 = VOFF + g * DH;

    #pragma unroll
    for (int i = 0; i < 4; i++) {
        int e = tid + i * 256, r = e >> 3, c = e & 7;
        CP_ASYNC16(sbase + r * (FRS * 2) + c * 16, QKV + (size_t)(qrow0 + r) * QKV_N + qcol0 + c * 8);
    }
    flash_load_kv(sbase + FSTG_OFF, tid, QKV, 0, kcol0, vcol0);
    flash_load_kv(sbase + FSTG_OFF + FSTG_BYTES, tid, QKV, 64, kcol0, vcol0);

    const uint32_t a_lane =
        (uint32_t)(((wid * 16 + (lane & 15)) * FRS + ((lane >> 4) << 3)) * 2);
    const uint32_t b_lane =
        (uint32_t)(((((lane >> 4) << 3) + (lane & 7)) * FRS + (((lane >> 3) & 1) << 3)) * 2);
    const uint32_t v_lane =
        (uint32_t)(((((lane >> 3) & 1) * 8 + (lane & 7)) * FRS + ((lane >> 4) << 3)) * 2);

    float oacc[8][4];
    #pragma unroll
    for (int t = 0; t < 8; t++)
        #pragma unroll
        for (int c = 0; c < 4; c++) oacc[t][c] = 0.0f;
    float m0 = -INFINITY, m1 = -INFINITY, l0 = 0.0f, l1 = 0.0f;

    for (int it = 0; it < FNIT; it++) {
        if (it < FNIT - 1) { CP_WAIT1(); } else { CP_WAIT0(); }
        __syncthreads();
        const uint32_t st = sbase + FSTG_OFF + (it & 1) * FSTG_BYTES;

        float sacc[8][4];
        #pragma unroll
        for (int t = 0; t < 8; t++)
            #pragma unroll
            for (int c = 0; c < 4; c++) sacc[t][c] = 0.0f;

        #pragma unroll
        for (int kk = 0; kk < 4; kk++) {
            const uint32_t koff = kk * 32;
            uint32_t ah[4];
            ldsm_x4(ah, sbase + a_lane + koff);
            uint32_t bh[4][4];
            #pragma unroll
            for (int j = 0; j < 4; j++)
                ldsm_x4(bh[j], st + b_lane + j * (16 * FRS * 2) + koff);
            #pragma unroll
            for (int t = 0; t < 8; t++)
                mma16816(sacc[t], ah, &bh[t >> 1][(t & 1) * 2]);
        }

        const float scale = 0.125f;
        float mx0 = -INFINITY, mx1 = -INFINITY;
        #pragma unroll
        for (int t = 0; t < 8; t++) {
            #pragma unroll
            for (int c = 0; c < 4; c++) sacc[t][c] *= scale;
            mx0 = fmaxf(mx0, fmaxf(sacc[t][0], sacc[t][1]));
            mx1 = fmaxf(mx1, fmaxf(sacc[t][2], sacc[t][3]));
        }
        mx0 = fmaxf(mx0, __shfl_xor_sync(0xffffffffu, mx0, 1));
        mx0 = fmaxf(mx0, __shfl_xor_sync(0xffffffffu, mx0, 2));
        mx1 = fmaxf(mx1, __shfl_xor_sync(0xffffffffu, mx1, 1));
        mx1 = fmaxf(mx1, __shfl_xor_sync(0xffffffffu, mx1, 2));
        const float mn0 = fmaxf(m0, mx0), mn1 = fmaxf(m1, mx1);
        const float corr0 = __expf(m0 - mn0), corr1 = __expf(m1 - mn1);
        m0 = mn0; m1 = mn1;

        float sum0 = 0.0f, sum1 = 0.0f;
        uint32_t pf[8][2];
        #pragma unroll
        for (int t = 0; t < 8; t++) {
            float p0 = __expf(sacc[t][0] - mn0), p1 = __expf(sacc[t][1] - mn0);
            float p2 = __expf(sacc[t][2] - mn1), p3 = __expf(sacc[t][3] - mn1);
            sum0 += p0 + p1; sum1 += p2 + p3;
            pf[t][0] = packh2(p0, p1);
            pf[t][1] = packh2(p2, p3);
        }
        sum0 += __shfl_xor_sync(0xffffffffu, sum0, 1);
        sum0 += __shfl_xor_sync(0xffffffffu, sum0, 2);
        sum1 += __shfl_xor_sync(0xffffffffu, sum1, 1);
        sum1 += __shfl_xor_sync(0xffffffffu, sum1, 2);
        l0 = l0 * corr0 + sum0;
        l1 = l1 * corr1 + sum1;
        #pragma unroll
        for (int t = 0; t < 8; t++) {
            oacc[t][0] *= corr0; oacc[t][1] *= corr0;
            oacc[t][2] *= corr1; oacc[t][3] *= corr1;
        }

        #pragma unroll
        for (int j = 0; j < 4; j++) {
            uint32_t ap[4] = { pf[2 * j][0], pf[2 * j][1], pf[2 * j + 1][0], pf[2 * j + 1][1] };
            #pragma unroll
            for (int nb = 0; nb < 4; nb++) {
                uint32_t vaddr = st + FKV_BYTES + v_lane + j * (16 * FRS * 2) + nb * 32;
                uint32_t vh[4];
                ldsm_x4_t(vh, vaddr);
                mma16816(oacc[2 * nb],     ap, &vh[0]);
                mma16816(oacc[2 * nb + 1], ap, &vh[2]);
            }
        }

        __syncthreads();
        if (it + 2 < FNIT)
            flash_load_kv(st, tid, QKV, (it + 2) * 64, kcol0, vcol0);
    }

    const float inv0 = 1.0f / l0, inv1 = 1.0f / l1;
    const int row0 = qrow0 + wid * 16 + (lane >> 2);
    const int row1 = row0 + 8;
    #pragma unroll
    for (int t = 0; t < 8; t++) {
        const int col = qcol0 + t * 8 + (lane & 3) * 2;
        *(uint32_t*)&Of[(size_t)row0 * DMODEL + col] =
            packh2(oacc[t][0] * inv0, oacc[t][1] * inv0);
        *(uint32_t*)&Of[(size_t)row1 * DMODEL + col] =
            packh2(oacc[t][2] * inv1, oacc[t][3] * inv1);
    }
}

// ============================ kernel_launch =================================
extern "C" void kernel_launch(void* const* d_in, const int* in_sizes, int n_in,
                              void* d_out, int out_size)
{
    const float* x  = (const float*)d_in[0];
    const float* wq = (const float*)d_in[1];
    const float* bq = (const float*)d_in[2];
    const float* wk = (const float*)d_in[3];
    const float* bk = (const float*)d_in[4];
    const float* wv = (const float*)d_in[5];
    const float* bv = (const float*)d_in[6];
    const float* wo = (const float*)d_in[7];
    const float* bo = (const float*)d_in[8];
    float* out = (float*)d_out;

    __half *xhi, *xlo, *QKV, *Of;
    __half *wFh, *wFl, *woF;
    float* bqkv;
    cudaGetSymbolAddress((void**)&xhi, g_xhi);
    cudaGetSymbolAddress((void**)&xlo, g_xlo);
    cudaGetSymbolAddress((void**)&QKV, g_QKV);
    cudaGetSymbolAddress((void**)&Of, g_Of);
    cudaGetSymbolAddress((void**)&wFh, g_wqkvF_hi);
    cudaGetSymbolAddress((void**)&wFl, g_wqkvF_lo);
    cudaGetSymbolAddress((void**)&woF, g_woF);
    cudaGetSymbolAddress((void**)&bqkv, g_bqkv);

    cudaFuncSetAttribute(gemm3, cudaFuncAttributeMaxDynamicSharedMemorySize, GEMM3_SMEM);
    cudaFuncSetAttribute(gemm1, cudaFuncAttributeMaxDynamicSharedMemorySize, GEMM1_SMEM);
    cudaFuncSetAttribute(flash_mma, cudaFuncAttributeMaxDynamicSharedMemorySize, FLASH_SMEM);

    const int nX = SEQ * DMODEL;

    cudaMemcpyAsync(bqkv,        bq, DMODEL * sizeof(float), cudaMemcpyDeviceToDevice);
    cudaMemcpyAsync(bqkv + KOFF, bk, DGROUP * sizeof(float), cudaMemcpyDeviceToDevice);
    cudaMemcpyAsync(bqkv + VOFF, bv, DGROUP * sizeof(float), cudaMemcpyDeviceToDevice);

    split_kernel<<<nX / (256 * 4), 256>>>(x, xhi, xlo, nX);
    // weights stay native [K, N]; scaled hi/lo split into fused [K, 5120]
    split_w<<<(KDIM * DMODEL) / (256 * 4), 256>>>(wq, wFh, wFl, DMODEL, 0);
    split_w<<<(KDIM * DGROUP) / (256 * 4), 256>>>(wk, wFh, wFl, DGROUP, KOFF);
    split_w<<<(KDIM * DGROUP) / (256 * 4), 256>>>(wv, wFh, wFl, DGROUP, VOFF);
    conv_half<<<(KDIM * DMODEL) / (256 * 4), 256>>>(wo, woF, KDIM * DMODEL);

    // fused QKV projection (3-product): [2048,4096] @ [4096,5120]
    gemm3<<<dim3(QKV_N / BN, SEQ / BM), 256, GEMM3_SMEM>>>(
        xhi, xlo, wFh, wFl, bqkv, QKV, QKV_N);

    flash_mma<<<dim3(SEQ / 128, NHEADS), 256, FLASH_SMEM>>>(QKV, Of);

    // O projection (1-product): [2048,4096] @ [4096,4096] -> fp32 out
    gemm1<<<dim3(DMODEL / BN, SEQ / BM), 256, GEMM1_SMEM>>>(Of, woF, bo, out, DMODEL);
}